// round 13
// baseline (speedup 1.0000x reference)
#include <cuda_runtime.h>
#include <math.h>

#define NN 100000
#define NE 3200000
#define NF 128
#define HH 16
#define NC 10

#define GEMM_BLKS ((NN + 127) / 128)                  // 782, 128 nodes/block, 1 thr/node
#define CNT_BLKS  ((2 * (NE / 4) + 127) / 128)        // 12500, int4 edge loads
#define FUSED_BLKS (GEMM_BLKS + CNT_BLKS)             // 13282; GEMM every 17th block

// ---------------- device scratch (zero-initialized at module load) -------------
__device__ int   g_cnt1[NN];    // re-zeroed by k_scale after use -> clean each call
__device__ int   g_cnt2[NN];
__device__ float g_dinv1[NN];
__device__ float g_dinv2[NN];
__device__ __align__(16) float g_y1[NN * 16];   // dinv1[i]*(x@W1)[i] after k_scale
__device__ __align__(16) float g_y2[NN * 16];
__device__ __align__(16) float g_acc1[NN * 16]; // seed = y (self-loop), + scatter
__device__ __align__(16) float g_acc2[NN * 16];
__device__ __align__(16) float g_yz[NN * 12];   // dinv1[i]*(h@W4)[i], stride 12
__device__ __align__(16) float g_acc3[NN * 12]; // seed = yz, + scatter

// 16-byte vector reduction straight to L2 (sm_90+).
__device__ __forceinline__ void red_add_v4(float* p, float4 v) {
    asm volatile("red.global.add.v4.f32 [%0], {%1,%2,%3,%4};"
                 :: "l"(__cvta_generic_to_global(p)),
                    "f"(v.x), "f"(v.y), "f"(v.z), "f"(v.w)
                 : "memory");
}

// ---------------- fused dual GEMM + degree count, INTERLEAVED -------------------
// GEMM block when bid % 17 == 0 (ids 0..781); otherwise a count block. This keeps
// the FFMA-bound GEMM work spread across the whole kernel so it hides entirely
// under the REDG-bound count floor instead of serializing after wave 1.
__global__ void __launch_bounds__(128) k_fused(
        const float* __restrict__ x,
        const float* __restrict__ W1,
        const float* __restrict__ W2,
        const int* __restrict__ dst1,
        const int* __restrict__ dst2) {
    __shared__ float Ws[NF * 32];
    int tid = threadIdx.x;
    int bid = blockIdx.x;

    if (bid % 17 != 0) {
        // ---- count block: index among non-GEMM blocks ----
        int cb = bid - (bid / 17 + 1);
        int id = cb * 128 + tid;                         // int4 index
        const int Q = NE / 4;                            // 800000
        if (id < Q) {
            int4 d = __ldg(&((const int4*)dst1)[id]);
            atomicAdd(&g_cnt1[d.x], 1);
            atomicAdd(&g_cnt1[d.y], 1);
            atomicAdd(&g_cnt1[d.z], 1);
            atomicAdd(&g_cnt1[d.w], 1);
        } else if (id < 2 * Q) {
            int4 d = __ldg(&((const int4*)dst2)[id - Q]);
            atomicAdd(&g_cnt2[d.x], 1);
            atomicAdd(&g_cnt2[d.y], 1);
            atomicAdd(&g_cnt2[d.z], 1);
            atomicAdd(&g_cnt2[d.w], 1);
        }
        return;
    }

    // ---- GEMM block ----
    int gb = bid / 17;                                   // 0..781
    for (int idx = tid; idx < NF * 32; idx += 128) {
        int k = idx >> 5, j = idx & 31;
        Ws[idx] = (j < HH) ? W1[k * HH + j] : W2[k * HH + (j - HH)];
    }
    __syncthreads();

    int i = gb * 128 + tid;
    if (i >= NN) return;

    float acc[32];
#pragma unroll
    for (int j = 0; j < 32; j++) acc[j] = 0.f;

    const float4* xrow = (const float4*)(x + (size_t)i * NF);
#pragma unroll 2
    for (int kk = 0; kk < NF / 4; kk++) {
        float4 xv = xrow[kk];
        const float* w = &Ws[(kk * 4) * 32];
#pragma unroll
        for (int j = 0; j < 32; j++) acc[j] += xv.x * w[j];
        w += 32;
#pragma unroll
        for (int j = 0; j < 32; j++) acc[j] += xv.y * w[j];
        w += 32;
#pragma unroll
        for (int j = 0; j < 32; j++) acc[j] += xv.z * w[j];
        w += 32;
#pragma unroll
        for (int j = 0; j < 32; j++) acc[j] += xv.w * w[j];
    }

    float* o1 = &g_y1[(size_t)i * 16];
    float* o2 = &g_y2[(size_t)i * 16];
#pragma unroll
    for (int q = 0; q < 4; q++) {
        *(float4*)(o1 + 4 * q) = make_float4(acc[4 * q], acc[4 * q + 1],
                                             acc[4 * q + 2], acc[4 * q + 3]);
        *(float4*)(o2 + 4 * q) = make_float4(acc[16 + 4 * q], acc[16 + 4 * q + 1],
                                             acc[16 + 4 * q + 2], acc[16 + 4 * q + 3]);
    }
}

// ---------------- scale: dinv from counts; y *= dinv; acc seed = y; re-zero cnt -
__global__ void k_scale() {
    unsigned t = blockIdx.x * blockDim.x + threadIdx.x;
    unsigned node = t >> 2;
    int q = t & 3;
    if (node >= NN) return;
    float d1 = rsqrtf((float)(g_cnt1[node] + 1));
    float d2 = rsqrtf((float)(g_cnt2[node] + 1));
    if (q == 0) {
        g_dinv1[node] = d1;
        g_dinv2[node] = d2;
        g_cnt1[node] = 0;   // leave counters clean for the next call/replay
        g_cnt2[node] = 0;
    }
    size_t o = (size_t)node * 16 + q * 4;
    float4 v1 = *(const float4*)(g_y1 + o);
    float4 v2 = *(const float4*)(g_y2 + o);
    v1.x *= d1; v1.y *= d1; v1.z *= d1; v1.w *= d1;
    v2.x *= d2; v2.y *= d2; v2.z *= d2; v2.w *= d2;
    *(float4*)(g_y1 + o) = v1;
    *(float4*)(g_y2 + o) = v2;
    *(float4*)(g_acc1 + o) = v1;   // self-loop seed (epilogue applies dinv)
    *(float4*)(g_acc2 + o) = v2;
}

// ---------------- quad-per-edge scatter, both graphs in one launch -------------
__global__ void __launch_bounds__(256) k_scatter16b(
        const int* __restrict__ src1, const int* __restrict__ dst1,
        const int* __restrict__ src2, const int* __restrict__ dst2) {
    unsigned t = blockIdx.x * 256u + threadIdx.x;
    unsigned e = t >> 2;
    int q = t & 3;
    if (e < NE) {
        int s = __ldg(src1 + e), d = __ldg(dst1 + e);
        float4 v = *(const float4*)(g_y1 + (size_t)s * 16 + q * 4);
        red_add_v4(g_acc1 + (size_t)d * 16 + q * 4, v);
    } else if (e < 2u * NE) {
        unsigned ee = e - NE;
        int s = __ldg(src2 + ee), d = __ldg(dst2 + ee);
        float4 v = *(const float4*)(g_y2 + (size_t)s * 16 + q * 4);
        red_add_v4(g_acc2 + (size_t)d * 16 + q * 4, v);
    }
}

// ---------------- combine: relu epilogue, concat, h @ W4, write yz + acc3 seed -
// (R11 scalar version — measured faster than the quad-lane variant.)
__global__ void k_combine(const float* __restrict__ b1,
                          const float* __restrict__ b2,
                          const float* __restrict__ W4) {
    __shared__ float sW4[32 * NC];
    __shared__ float sb1[HH], sb2[HH];
    int tid = threadIdx.x;
    for (int t = tid; t < 32 * NC; t += blockDim.x) sW4[t] = W4[t];
    if (tid < HH) { sb1[tid] = b1[tid]; sb2[tid] = b2[tid]; }
    __syncthreads();

    int i = blockIdx.x * blockDim.x + tid;
    if (i >= NN) return;

    float d1 = g_dinv1[i], d2 = g_dinv2[i];
    float h[32];
    const float* a1 = &g_acc1[(size_t)i * 16];
    const float* a2 = &g_acc2[(size_t)i * 16];
#pragma unroll
    for (int j = 0; j < 16; j++) {
        h[j]      = fmaxf(d1 * a1[j] + sb1[j], 0.f);
        h[16 + j] = fmaxf(d2 * a2[j] + sb2[j], 0.f);
    }

    float z[NC];
#pragma unroll
    for (int c = 0; c < NC; c++) z[c] = 0.f;
#pragma unroll
    for (int j = 0; j < 32; j++) {
        float hj = h[j];
#pragma unroll
        for (int c = 0; c < NC; c++) z[c] += hj * sW4[j * NC + c];
    }

    float* o = &g_yz[(size_t)i * 12];
    float* a = &g_acc3[(size_t)i * 12];
#pragma unroll
    for (int c = 0; c < NC; c++) {
        float yz = d1 * z[c];
        o[c] = yz;
        a[c] = yz;          // self-loop seed (epilogue applies dinv)
    }
    o[10] = 0.f; o[11] = 0.f;
    a[10] = 0.f; a[11] = 0.f;
}

// ---------------- 3-lanes-per-edge scatter for 12-padded logits ----------------
__global__ void __launch_bounds__(384) k_scatter10q(const int* __restrict__ src,
                                                    const int* __restrict__ dst) {
    unsigned t = blockIdx.x * 384u + threadIdx.x;
    unsigned e = t / 3u;
    int q = (int)(t - e * 3u);
    if (e >= NE) return;
    int s = __ldg(src + e), d = __ldg(dst + e);
    float4 v = *(const float4*)(&g_yz[(size_t)s * 12] + q * 4);
    red_add_v4(&g_acc3[(size_t)d * 12] + q * 4, v);
}

// ---------------- final: conv3 epilogue + log_softmax ----------------
__global__ void k_final(const float* __restrict__ b4, float* __restrict__ out) {
    int i = blockIdx.x * blockDim.x + threadIdx.x;
    if (i >= NN) return;

    float d1 = g_dinv1[i];
    float l[NC];
    const float* a = &g_acc3[(size_t)i * 12];
#pragma unroll
    for (int c = 0; c < NC; c++) l[c] = d1 * a[c] + __ldg(b4 + c);

    float m = l[0];
#pragma unroll
    for (int c = 1; c < NC; c++) m = fmaxf(m, l[c]);
    float s = 0.f;
#pragma unroll
    for (int c = 0; c < NC; c++) s += expf(l[c] - m);
    float lse = m + logf(s);
#pragma unroll
    for (int c = 0; c < NC; c++) out[(size_t)i * NC + c] = l[c] - lse;
}

// ---------------- launch ----------------
extern "C" void kernel_launch(void* const* d_in, const int* in_sizes, int n_in,
                              void* d_out, int out_size) {
    const float* x  = (const float*)d_in[0];
    const int*   ei = (const int*)d_in[1];   // [2, NE] int32: row0 src, row1 dst
    const int*   tp = (const int*)d_in[2];
    const float* W1 = (const float*)d_in[3];
    const float* b1 = (const float*)d_in[4];
    const float* W2 = (const float*)d_in[5];
    const float* b2 = (const float*)d_in[6];
    const float* W4 = (const float*)d_in[7];
    const float* b4 = (const float*)d_in[8];
    float* out = (float*)d_out;

    k_fused<<<FUSED_BLKS, 128>>>(x, W1, W2, ei + NE, tp + NE);

    k_scale<<<(4 * NN + 255) / 256, 256>>>();

    k_scatter16b<<<(8u * NE + 255) / 256, 256>>>(ei, ei + NE, tp, tp + NE);

    k_combine<<<(NN + 255) / 256, 256>>>(b1, b2, W4);

    k_scatter10q<<<(3u * NE + 383) / 384, 384>>>(ei, ei + NE);

    k_final<<<(NN + 255) / 256, 256>>>(b4, out);
}

// round 14
// speedup vs baseline: 1.0791x; 1.0791x over previous
#include <cuda_runtime.h>
#include <math.h>

#define NN 100000
#define NE 3200000
#define NF 128
#define HH 16
#define NC 10

#define GEMM_BLKS ((NN + 127) / 128)                  // 782, 128 nodes/block, 1 thr/node
#define CNT_BLKS  ((2 * (NE / 8) + 127) / 128)        // 6250, 2x int4 per thread

// ---------------- device scratch (zero-initialized at module load) -------------
__device__ int   g_cnt1[NN];    // re-zeroed by k_scale after use -> clean each call
__device__ int   g_cnt2[NN];
__device__ float g_dinv1[NN];
__device__ float g_dinv2[NN];
__device__ __align__(16) float g_y1[NN * 16];   // dinv1[i]*(x@W1)[i] after k_scale
__device__ __align__(16) float g_y2[NN * 16];
__device__ __align__(16) float g_acc1[NN * 16]; // seed = y (self-loop), + scatter
__device__ __align__(16) float g_acc2[NN * 16];
__device__ __align__(16) float g_yz[NN * 12];   // dinv1[i]*(h@W4)[i], stride 12
__device__ __align__(16) float g_acc3[NN * 12]; // seed = yz, + scatter

// 16-byte vector reduction straight to L2 (sm_90+).
__device__ __forceinline__ void red_add_v4(float* p, float4 v) {
    asm volatile("red.global.add.v4.f32 [%0], {%1,%2,%3,%4};"
                 :: "l"(__cvta_generic_to_global(p)),
                    "f"(v.x), "f"(v.y), "f"(v.z), "f"(v.w)
                 : "memory");
}

// ---------------- fused: [0..GEMM_BLKS) dual GEMM | rest: degree count ----------
// GEMM blocks FIRST: all 782 land in wave 1 and hide under the count REDG floor.
// Count threads each process 2 independent int4 (8 edges) for MLP + fewer blocks.
__global__ void __launch_bounds__(128) k_fused(
        const float* __restrict__ x,
        const float* __restrict__ W1,
        const float* __restrict__ W2,
        const int* __restrict__ dst1,
        const int* __restrict__ dst2) {
    __shared__ float Ws[NF * 32];
    int tid = threadIdx.x;

    if (blockIdx.x >= GEMM_BLKS) {
        int id = ((blockIdx.x - GEMM_BLKS) * 128 + tid) * 2;  // int4 index, 2 per thread
        const int Q = NE / 4;                                 // 800000 int4 per list
        if (id < Q) {
            int4 a = __ldg(&((const int4*)dst1)[id]);
            int4 b = __ldg(&((const int4*)dst1)[id + 1]);
            atomicAdd(&g_cnt1[a.x], 1);
            atomicAdd(&g_cnt1[a.y], 1);
            atomicAdd(&g_cnt1[a.z], 1);
            atomicAdd(&g_cnt1[a.w], 1);
            atomicAdd(&g_cnt1[b.x], 1);
            atomicAdd(&g_cnt1[b.y], 1);
            atomicAdd(&g_cnt1[b.z], 1);
            atomicAdd(&g_cnt1[b.w], 1);
        } else if (id < 2 * Q) {
            int4 a = __ldg(&((const int4*)dst2)[id - Q]);
            int4 b = __ldg(&((const int4*)dst2)[id - Q + 1]);
            atomicAdd(&g_cnt2[a.x], 1);
            atomicAdd(&g_cnt2[a.y], 1);
            atomicAdd(&g_cnt2[a.z], 1);
            atomicAdd(&g_cnt2[a.w], 1);
            atomicAdd(&g_cnt2[b.x], 1);
            atomicAdd(&g_cnt2[b.y], 1);
            atomicAdd(&g_cnt2[b.z], 1);
            atomicAdd(&g_cnt2[b.w], 1);
        }
        return;
    }

    // ---- GEMM part ----
    for (int idx = tid; idx < NF * 32; idx += 128) {
        int k = idx >> 5, j = idx & 31;
        Ws[idx] = (j < HH) ? W1[k * HH + j] : W2[k * HH + (j - HH)];
    }
    __syncthreads();

    int i = blockIdx.x * 128 + tid;
    if (i >= NN) return;

    float acc[32];
#pragma unroll
    for (int j = 0; j < 32; j++) acc[j] = 0.f;

    const float4* xrow = (const float4*)(x + (size_t)i * NF);
#pragma unroll 2
    for (int kk = 0; kk < NF / 4; kk++) {
        float4 xv = xrow[kk];
        const float* w = &Ws[(kk * 4) * 32];
#pragma unroll
        for (int j = 0; j < 32; j++) acc[j] += xv.x * w[j];
        w += 32;
#pragma unroll
        for (int j = 0; j < 32; j++) acc[j] += xv.y * w[j];
        w += 32;
#pragma unroll
        for (int j = 0; j < 32; j++) acc[j] += xv.z * w[j];
        w += 32;
#pragma unroll
        for (int j = 0; j < 32; j++) acc[j] += xv.w * w[j];
    }

    float* o1 = &g_y1[(size_t)i * 16];
    float* o2 = &g_y2[(size_t)i * 16];
#pragma unroll
    for (int q = 0; q < 4; q++) {
        *(float4*)(o1 + 4 * q) = make_float4(acc[4 * q], acc[4 * q + 1],
                                             acc[4 * q + 2], acc[4 * q + 3]);
        *(float4*)(o2 + 4 * q) = make_float4(acc[16 + 4 * q], acc[16 + 4 * q + 1],
                                             acc[16 + 4 * q + 2], acc[16 + 4 * q + 3]);
    }
}

// ---------------- scale: dinv from counts; y *= dinv; acc seed = y; re-zero cnt -
__global__ void k_scale() {
    unsigned t = blockIdx.x * blockDim.x + threadIdx.x;
    unsigned node = t >> 2;
    int q = t & 3;
    if (node >= NN) return;
    float d1 = rsqrtf((float)(g_cnt1[node] + 1));
    float d2 = rsqrtf((float)(g_cnt2[node] + 1));
    if (q == 0) {
        g_dinv1[node] = d1;
        g_dinv2[node] = d2;
        g_cnt1[node] = 0;   // leave counters clean for the next call/replay
        g_cnt2[node] = 0;
    }
    size_t o = (size_t)node * 16 + q * 4;
    float4 v1 = *(const float4*)(g_y1 + o);
    float4 v2 = *(const float4*)(g_y2 + o);
    v1.x *= d1; v1.y *= d1; v1.z *= d1; v1.w *= d1;
    v2.x *= d2; v2.y *= d2; v2.z *= d2; v2.w *= d2;
    *(float4*)(g_y1 + o) = v1;
    *(float4*)(g_y2 + o) = v2;
    *(float4*)(g_acc1 + o) = v1;   // self-loop seed (epilogue applies dinv)
    *(float4*)(g_acc2 + o) = v2;
}

// ---------------- quad-per-edge scatter, both graphs in one launch -------------
__global__ void __launch_bounds__(256) k_scatter16b(
        const int* __restrict__ src1, const int* __restrict__ dst1,
        const int* __restrict__ src2, const int* __restrict__ dst2) {
    unsigned t = blockIdx.x * 256u + threadIdx.x;
    unsigned e = t >> 2;
    int q = t & 3;
    if (e < NE) {
        int s = __ldg(src1 + e), d = __ldg(dst1 + e);
        float4 v = *(const float4*)(g_y1 + (size_t)s * 16 + q * 4);
        red_add_v4(g_acc1 + (size_t)d * 16 + q * 4, v);
    } else if (e < 2u * NE) {
        unsigned ee = e - NE;
        int s = __ldg(src2 + ee), d = __ldg(dst2 + ee);
        float4 v = *(const float4*)(g_y2 + (size_t)s * 16 + q * 4);
        red_add_v4(g_acc2 + (size_t)d * 16 + q * 4, v);
    }
}

// ---------------- combine: relu epilogue, concat, h @ W4, write yz + acc3 seed -
__global__ void k_combine(const float* __restrict__ b1,
                          const float* __restrict__ b2,
                          const float* __restrict__ W4) {
    __shared__ float sW4[32 * NC];
    __shared__ float sb1[HH], sb2[HH];
    int tid = threadIdx.x;
    for (int t = tid; t < 32 * NC; t += blockDim.x) sW4[t] = W4[t];
    if (tid < HH) { sb1[tid] = b1[tid]; sb2[tid] = b2[tid]; }
    __syncthreads();

    int i = blockIdx.x * blockDim.x + tid;
    if (i >= NN) return;

    float d1 = g_dinv1[i], d2 = g_dinv2[i];
    float h[32];
    const float* a1 = &g_acc1[(size_t)i * 16];
    const float* a2 = &g_acc2[(size_t)i * 16];
#pragma unroll
    for (int j = 0; j < 16; j++) {
        h[j]      = fmaxf(d1 * a1[j] + sb1[j], 0.f);
        h[16 + j] = fmaxf(d2 * a2[j] + sb2[j], 0.f);
    }

    float z[NC];
#pragma unroll
    for (int c = 0; c < NC; c++) z[c] = 0.f;
#pragma unroll
    for (int j = 0; j < 32; j++) {
        float hj = h[j];
#pragma unroll
        for (int c = 0; c < NC; c++) z[c] += hj * sW4[j * NC + c];
    }

    float* o = &g_yz[(size_t)i * 12];
    float* a = &g_acc3[(size_t)i * 12];
#pragma unroll
    for (int c = 0; c < NC; c++) {
        float yz = d1 * z[c];
        o[c] = yz;
        a[c] = yz;          // self-loop seed (epilogue applies dinv)
    }
    o[10] = 0.f; o[11] = 0.f;
    a[10] = 0.f; a[11] = 0.f;
}

// ---------------- 3-lanes-per-edge scatter for 12-padded logits ----------------
__global__ void __launch_bounds__(384) k_scatter10q(const int* __restrict__ src,
                                                    const int* __restrict__ dst) {
    unsigned t = blockIdx.x * 384u + threadIdx.x;
    unsigned e = t / 3u;
    int q = (int)(t - e * 3u);
    if (e >= NE) return;
    int s = __ldg(src + e), d = __ldg(dst + e);
    float4 v = *(const float4*)(&g_yz[(size_t)s * 12] + q * 4);
    red_add_v4(&g_acc3[(size_t)d * 12] + q * 4, v);
}

// ---------------- final: conv3 epilogue + log_softmax ----------------
__global__ void k_final(const float* __restrict__ b4, float* __restrict__ out) {
    int i = blockIdx.x * blockDim.x + threadIdx.x;
    if (i >= NN) return;

    float d1 = g_dinv1[i];
    float l[NC];
    const float* a = &g_acc3[(size_t)i * 12];
#pragma unroll
    for (int c = 0; c < NC; c++) l[c] = d1 * a[c] + __ldg(b4 + c);

    float m = l[0];
#pragma unroll
    for (int c = 1; c < NC; c++) m = fmaxf(m, l[c]);
    float s = 0.f;
#pragma unroll
    for (int c = 0; c < NC; c++) s += expf(l[c] - m);
    float lse = m + logf(s);
#pragma unroll
    for (int c = 0; c < NC; c++) out[(size_t)i * NC + c] = l[c] - lse;
}

// ---------------- launch ----------------
extern "C" void kernel_launch(void* const* d_in, const int* in_sizes, int n_in,
                              void* d_out, int out_size) {
    const float* x  = (const float*)d_in[0];
    const int*   ei = (const int*)d_in[1];   // [2, NE] int32: row0 src, row1 dst
    const int*   tp = (const int*)d_in[2];
    const float* W1 = (const float*)d_in[3];
    const float* b1 = (const float*)d_in[4];
    const float* W2 = (const float*)d_in[5];
    const float* b2 = (const float*)d_in[6];
    const float* W4 = (const float*)d_in[7];
    const float* b4 = (const float*)d_in[8];
    float* out = (float*)d_out;

    k_fused<<<GEMM_BLKS + CNT_BLKS, 128>>>(x, W1, W2, ei + NE, tp + NE);

    k_scale<<<(4 * NN + 255) / 256, 256>>>();

    k_scatter16b<<<(8u * NE + 255) / 256, 256>>>(ei, ei + NE, tp, tp + NE);

    k_combine<<<(NN + 255) / 256, 256>>>(b1, b2, W4);

    k_scatter10q<<<(3u * NE + 383) / 384, 384>>>(ei, ei + NE);

    k_final<<<(NN + 255) / 256, 256>>>(b4, out);
}

// round 15
// speedup vs baseline: 1.1102x; 1.0288x over previous
#include <cuda_runtime.h>
#include <math.h>

#define NN 100000
#define NE 3200000
#define NF 128
#define HH 16
#define NC 10

#define GEMM_BLKS ((NN + 127) / 128)                  // 782, 128 nodes/block, 1 thr/node
#define CNT_BLKS  ((2 * (NE / 4) + 127) / 128)        // 12500, int4 edge loads

// ---------------- device scratch (zero-initialized at module load) -------------
__device__ int   g_cnt1[NN];    // re-zeroed by k_scale after use -> clean each call
__device__ int   g_cnt2[NN];
__device__ float g_dinv1[NN];
__device__ float g_dinv2[NN];
__device__ __align__(16) float g_y1[NN * 16];   // dinv1[i]*(x@W1)[i] after k_scale
__device__ __align__(16) float g_y2[NN * 16];
__device__ __align__(16) float g_acc1[NN * 16]; // seed = y (self-loop), + scatter
__device__ __align__(16) float g_acc2[NN * 16];
__device__ __align__(16) float g_yz[NN * 12];   // dinv1[i]*(h@W4)[i], stride 12
__device__ __align__(16) float g_acc3[NN * 12]; // seed = yz, + scatter

// 16-byte vector reduction straight to L2 (sm_90+).
__device__ __forceinline__ void red_add_v4(float* p, float4 v) {
    asm volatile("red.global.add.v4.f32 [%0], {%1,%2,%3,%4};"
                 :: "l"(__cvta_generic_to_global(p)),
                    "f"(v.x), "f"(v.y), "f"(v.z), "f"(v.w)
                 : "memory");
}

// ---------------- fused: [0..GEMM_BLKS) dual GEMM | rest: degree count ----------
// GEMM blocks FIRST: all 782 land in wave 1 and hide under the count REDG floor.
__global__ void __launch_bounds__(128) k_fused(
        const float* __restrict__ x,
        const float* __restrict__ W1,
        const float* __restrict__ W2,
        const int* __restrict__ dst1,
        const int* __restrict__ dst2) {
    __shared__ float Ws[NF * 32];
    int tid = threadIdx.x;

    if (blockIdx.x >= GEMM_BLKS) {
        int id = (blockIdx.x - GEMM_BLKS) * 128 + tid;   // int4 index
        const int Q = NE / 4;                            // 800000
        if (id < Q) {
            int4 d = __ldg(&((const int4*)dst1)[id]);
            atomicAdd(&g_cnt1[d.x], 1);
            atomicAdd(&g_cnt1[d.y], 1);
            atomicAdd(&g_cnt1[d.z], 1);
            atomicAdd(&g_cnt1[d.w], 1);
        } else if (id < 2 * Q) {
            int4 d = __ldg(&((const int4*)dst2)[id - Q]);
            atomicAdd(&g_cnt2[d.x], 1);
            atomicAdd(&g_cnt2[d.y], 1);
            atomicAdd(&g_cnt2[d.z], 1);
            atomicAdd(&g_cnt2[d.w], 1);
        }
        return;
    }

    // ---- GEMM part ----
    for (int idx = tid; idx < NF * 32; idx += 128) {
        int k = idx >> 5, j = idx & 31;
        Ws[idx] = (j < HH) ? W1[k * HH + j] : W2[k * HH + (j - HH)];
    }
    __syncthreads();

    int i = blockIdx.x * 128 + tid;
    if (i >= NN) return;

    float acc[32];
#pragma unroll
    for (int j = 0; j < 32; j++) acc[j] = 0.f;

    const float4* xrow = (const float4*)(x + (size_t)i * NF);
#pragma unroll 2
    for (int kk = 0; kk < NF / 4; kk++) {
        float4 xv = xrow[kk];
        const float* w = &Ws[(kk * 4) * 32];
#pragma unroll
        for (int j = 0; j < 32; j++) acc[j] += xv.x * w[j];
        w += 32;
#pragma unroll
        for (int j = 0; j < 32; j++) acc[j] += xv.y * w[j];
        w += 32;
#pragma unroll
        for (int j = 0; j < 32; j++) acc[j] += xv.z * w[j];
        w += 32;
#pragma unroll
        for (int j = 0; j < 32; j++) acc[j] += xv.w * w[j];
    }

    float* o1 = &g_y1[(size_t)i * 16];
    float* o2 = &g_y2[(size_t)i * 16];
#pragma unroll
    for (int q = 0; q < 4; q++) {
        *(float4*)(o1 + 4 * q) = make_float4(acc[4 * q], acc[4 * q + 1],
                                             acc[4 * q + 2], acc[4 * q + 3]);
        *(float4*)(o2 + 4 * q) = make_float4(acc[16 + 4 * q], acc[16 + 4 * q + 1],
                                             acc[16 + 4 * q + 2], acc[16 + 4 * q + 3]);
    }
}

// ---------------- scale: dinv from counts; y *= dinv; acc seed = y; re-zero cnt -
__global__ void k_scale() {
    unsigned t = blockIdx.x * blockDim.x + threadIdx.x;
    unsigned node = t >> 2;
    int q = t & 3;
    if (node >= NN) return;
    float d1 = rsqrtf((float)(g_cnt1[node] + 1));
    float d2 = rsqrtf((float)(g_cnt2[node] + 1));
    if (q == 0) {
        g_dinv1[node] = d1;
        g_dinv2[node] = d2;
        g_cnt1[node] = 0;   // leave counters clean for the next call/replay
        g_cnt2[node] = 0;
    }
    size_t o = (size_t)node * 16 + q * 4;
    float4 v1 = *(const float4*)(g_y1 + o);
    float4 v2 = *(const float4*)(g_y2 + o);
    v1.x *= d1; v1.y *= d1; v1.z *= d1; v1.w *= d1;
    v2.x *= d2; v2.y *= d2; v2.z *= d2; v2.w *= d2;
    *(float4*)(g_y1 + o) = v1;
    *(float4*)(g_y2 + o) = v2;
    *(float4*)(g_acc1 + o) = v1;   // self-loop seed (epilogue applies dinv)
    *(float4*)(g_acc2 + o) = v2;
}

// ---------------- quad-per-edge scatter, both graphs in one launch -------------
__global__ void __launch_bounds__(256) k_scatter16b(
        const int* __restrict__ src1, const int* __restrict__ dst1,
        const int* __restrict__ src2, const int* __restrict__ dst2) {
    unsigned t = blockIdx.x * 256u + threadIdx.x;
    unsigned e = t >> 2;
    int q = t & 3;
    if (e < NE) {
        int s = __ldg(src1 + e), d = __ldg(dst1 + e);
        float4 v = *(const float4*)(g_y1 + (size_t)s * 16 + q * 4);
        red_add_v4(g_acc1 + (size_t)d * 16 + q * 4, v);
    } else if (e < 2u * NE) {
        unsigned ee = e - NE;
        int s = __ldg(src2 + ee), d = __ldg(dst2 + ee);
        float4 v = *(const float4*)(g_y2 + (size_t)s * 16 + q * 4);
        red_add_v4(g_acc2 + (size_t)d * 16 + q * 4, v);
    }
}

// ---------------- combine: relu epilogue, concat, h @ W4, write yz + acc3 seed -
__global__ void k_combine(const float* __restrict__ b1,
                          const float* __restrict__ b2,
                          const float* __restrict__ W4) {
    __shared__ float sW4[32 * NC];
    __shared__ float sb1[HH], sb2[HH];
    int tid = threadIdx.x;
    for (int t = tid; t < 32 * NC; t += blockDim.x) sW4[t] = W4[t];
    if (tid < HH) { sb1[tid] = b1[tid]; sb2[tid] = b2[tid]; }
    __syncthreads();

    int i = blockIdx.x * blockDim.x + tid;
    if (i >= NN) return;

    float d1 = g_dinv1[i], d2 = g_dinv2[i];
    float h[32];
    const float* a1 = &g_acc1[(size_t)i * 16];
    const float* a2 = &g_acc2[(size_t)i * 16];
#pragma unroll
    for (int j = 0; j < 16; j++) {
        h[j]      = fmaxf(d1 * a1[j] + sb1[j], 0.f);
        h[16 + j] = fmaxf(d2 * a2[j] + sb2[j], 0.f);
    }

    float z[NC];
#pragma unroll
    for (int c = 0; c < NC; c++) z[c] = 0.f;
#pragma unroll
    for (int j = 0; j < 32; j++) {
        float hj = h[j];
#pragma unroll
        for (int c = 0; c < NC; c++) z[c] += hj * sW4[j * NC + c];
    }

    float* o = &g_yz[(size_t)i * 12];
    float* a = &g_acc3[(size_t)i * 12];
#pragma unroll
    for (int c = 0; c < NC; c++) {
        float yz = d1 * z[c];
        o[c] = yz;
        a[c] = yz;          // self-loop seed (epilogue applies dinv)
    }
    o[10] = 0.f; o[11] = 0.f;
    a[10] = 0.f; a[11] = 0.f;
}

// ---------------- 3-lanes-per-edge scatter for 12-padded logits ----------------
__global__ void __launch_bounds__(192) k_scatter10q(const int* __restrict__ src,
                                                    const int* __restrict__ dst) {
    unsigned t = blockIdx.x * 192u + threadIdx.x;
    unsigned e = t / 3u;
    int q = (int)(t - e * 3u);
    if (e >= NE) return;
    int s = __ldg(src + e), d = __ldg(dst + e);
    float4 v = *(const float4*)(&g_yz[(size_t)s * 12] + q * 4);
    red_add_v4(&g_acc3[(size_t)d * 12] + q * 4, v);
}

// ---------------- final: conv3 epilogue + log_softmax ----------------
__global__ void k_final(const float* __restrict__ b4, float* __restrict__ out) {
    int i = blockIdx.x * blockDim.x + threadIdx.x;
    if (i >= NN) return;

    float d1 = g_dinv1[i];
    float l[NC];
    const float* a = &g_acc3[(size_t)i * 12];
#pragma unroll
    for (int c = 0; c < NC; c++) l[c] = d1 * a[c] + __ldg(b4 + c);

    float m = l[0];
#pragma unroll
    for (int c = 1; c < NC; c++) m = fmaxf(m, l[c]);
    float s = 0.f;
#pragma unroll
    for (int c = 0; c < NC; c++) s += expf(l[c] - m);
    float lse = m + logf(s);
#pragma unroll
    for (int c = 0; c < NC; c++) out[(size_t)i * NC + c] = l[c] - lse;
}

// ---------------- launch ----------------
extern "C" void kernel_launch(void* const* d_in, const int* in_sizes, int n_in,
                              void* d_out, int out_size) {
    const float* x  = (const float*)d_in[0];
    const int*   ei = (const int*)d_in[1];   // [2, NE] int32: row0 src, row1 dst
    const int*   tp = (const int*)d_in[2];
    const float* W1 = (const float*)d_in[3];
    const float* b1 = (const float*)d_in[4];
    const float* W2 = (const float*)d_in[5];
    const float* b2 = (const float*)d_in[6];
    const float* W4 = (const float*)d_in[7];
    const float* b4 = (const float*)d_in[8];
    float* out = (float*)d_out;

    k_fused<<<GEMM_BLKS + CNT_BLKS, 128>>>(x, W1, W2, ei + NE, tp + NE);

    k_scale<<<(4 * NN + 255) / 256, 256>>>();

    k_scatter16b<<<(8u * NE + 255) / 256, 256>>>(ei, ei + NE, tp, tp + NE);

    k_combine<<<(NN + 255) / 256, 256>>>(b1, b2, W4);

    k_scatter10q<<<(3u * NE + 191) / 192, 192>>>(ei, ei + NE);

    k_final<<<(NN + 255) / 256, 256>>>(b4, out);
}